// round 1
// baseline (speedup 1.0000x reference)
#include <cuda_runtime.h>
#include <math.h>

#define BB 8
#define SS 256
#define HH 100
#define PP 20
#define EPSF 1e-8f
#define NTOK (BB*SS)      // 2048 per side
#define OD 105
#define NEGINF -3.0e38f

// ---------------- scratch (device globals; no runtime allocation) ----------------
__device__ float g_cp[NTOK*HH], g_ch[NTOK*HH];     // masked contexts
__device__ float g_np[NTOK], g_nh[NTOK];           // unweighted norms
__device__ float g_wn[2][4][NTOK*PP];              // [side][w: full,maxpool,att,maxatt][tok*P+p]
__device__ int   g_len[2][BB];
__device__ float g_last[2][BB*HH];                 // [0]=last_p, [1]=last_h
__device__ float g_cos[BB*SS*SS];
__device__ float g_rowsum[NTOK], g_colsum[NTOK];
__device__ float g_att_mean[2][NTOK*HH];           // [0]=att_mean_h (v2 for p side), [1]=att_mean_p
__device__ float g_att_max[2][NTOK*HH];
__device__ float g_num[BB*SS*PP*SS];               // [b][m=i*P+p][j], 42MB

// ---------------- K0: per-token prep: masked ctx, norms, weighted norms ----------
__global__ void k_prep(const float* __restrict__ ctx_p, const int* __restrict__ mask_p,
                       const float* __restrict__ ctx_h, const int* __restrict__ mask_h,
                       const float* __restrict__ w_full, const float* __restrict__ w_mp,
                       const float* __restrict__ w_att, const float* __restrict__ w_ma)
{
    __shared__ float vsq[8][HH];
    int wl = threadIdx.x >> 5;
    int lane = threadIdx.x & 31;
    int gw = blockIdx.x * 8 + wl;            // 0..4095
    int side = gw / NTOK;
    int tok = gw % NTOK;
    const float* ctx = side ? ctx_h : ctx_p;
    const int* mask = side ? mask_h : mask_p;
    float* dst = side ? g_ch : g_cp;
    float m = (float)mask[tok];
    float q = 0.f;
    for (int h = lane; h < HH; h += 32) {
        float v = ctx[tok*HH + h] * m;
        dst[tok*HH + h] = v;
        float v2 = v * v;
        vsq[wl][h] = v2;
        q += v2;
    }
    #pragma unroll
    for (int o = 16; o; o >>= 1) q += __shfl_xor_sync(0xffffffffu, q, o);
    if (lane == 0) (side ? g_nh : g_np)[tok] = sqrtf(q);
    __syncwarp();
    const float* ws[4] = {w_full, w_mp, w_att, w_ma};
    for (int c = lane; c < 4*PP; c += 32) {
        int w = c / PP, p = c % PP;
        const float* wr = ws[w] + p*HH;
        float s = 0.f;
        #pragma unroll 4
        for (int h = 0; h < HH; h++) { float ww = wr[h]; s += ww*ww*vsq[wl][h]; }
        g_wn[side][w][tok*PP + p] = sqrtf(s);
    }
}

// ---------------- K0b: lengths + last valid token vectors ------------------------
__global__ void k_len_last(const int* __restrict__ mask_p, const int* __restrict__ mask_h)
{
    int w = threadIdx.x >> 5;        // 0..15
    int lane = threadIdx.x & 31;
    int side = w / BB, b = w % BB;
    const int* mask = side ? mask_h : mask_p;
    int s = 0;
    for (int j = lane; j < SS; j += 32) s += mask[b*SS + j];
    #pragma unroll
    for (int o = 16; o; o >>= 1) s += __shfl_xor_sync(0xffffffffu, s, o);
    if (lane == 0) g_len[side][b] = s;
    s = __shfl_sync(0xffffffffu, s, 0);
    int last = s > 0 ? s - 1 : 0;
    const float* src = (side ? g_ch : g_cp) + (b*SS + last)*HH;
    float* dst = g_last[side] + b*HH;
    for (int h = lane; h < HH; h += 32) dst[h] = src[h];
}

// ---------------- K1: pairwise cosine (8 GEMMs 256x256x100) ----------------------
__global__ void k_cos()
{
    int b = blockIdx.z, it = blockIdx.y, jt = blockIdx.x;
    __shared__ float As[20][64], Bs[20][64];
    int t = threadIdx.x;
    int tx = t & 15, ty = t >> 4;
    float acc[4][4] = {};
    const float* Ap = g_cp + (b*SS + it*64)*HH;
    const float* Bp = g_ch + (b*SS + jt*64)*HH;
    for (int k0 = 0; k0 < HH; k0 += 20) {
        __syncthreads();
        for (int e = t; e < 64*20; e += 256) {
            int mm = e / 20, kc = e % 20;
            As[kc][mm] = Ap[mm*HH + k0 + kc];
            Bs[kc][mm] = Bp[mm*HH + k0 + kc];
        }
        __syncthreads();
        #pragma unroll
        for (int kc = 0; kc < 20; kc++) {
            float a[4], bb[4];
            #pragma unroll
            for (int r = 0; r < 4; r++) a[r] = As[kc][ty*4 + r];
            #pragma unroll
            for (int c = 0; c < 4; c++) bb[c] = Bs[kc][tx*4 + c];
            #pragma unroll
            for (int r = 0; r < 4; r++)
                #pragma unroll
                for (int c = 0; c < 4; c++) acc[r][c] += a[r]*bb[c];
        }
    }
    #pragma unroll
    for (int r = 0; r < 4; r++) {
        int i = it*64 + ty*4 + r;
        float ni = fmaxf(g_np[b*SS + i], EPSF);
        #pragma unroll
        for (int c = 0; c < 4; c++) {
            int j = jt*64 + tx*4 + c;
            float nj = fmaxf(g_nh[b*SS + j], EPSF);
            g_cos[(b*SS + i)*SS + j] = acc[r][c] / (ni*nj);
        }
    }
}

// ---------------- K2: cos row/col reductions (max, mean, sums for attention) -----
__global__ void k_cosred_row(float* __restrict__ out)
{
    int gw = blockIdx.x*8 + (threadIdx.x >> 5);   // b*S+i
    int lane = threadIdx.x & 31;
    int b = gw / SS, i = gw % SS;
    int lh = g_len[1][b];
    const float* row = g_cos + gw*SS;
    float sm = 0.f, mx = NEGINF;
    for (int j = lane; j < SS; j += 32) {
        float v = row[j];
        sm += v;
        if (j < lh) mx = fmaxf(mx, v);
    }
    #pragma unroll
    for (int o = 16; o; o >>= 1) {
        sm += __shfl_xor_sync(0xffffffffu, sm, o);
        mx = fmaxf(mx, __shfl_xor_sync(0xffffffffu, mx, o));
    }
    if (lane == 0) {
        g_rowsum[gw] = sm;
        float* o = out + (size_t)(b*SS + i)*OD;
        o[0] = mx;
        o[1] = sm / (float)lh;
    }
}

__global__ void k_cosred_col(float* __restrict__ out)
{
    int gw = blockIdx.x*8 + (threadIdx.x >> 5);   // b*S+j
    int lane = threadIdx.x & 31;
    int b = gw / SS, j = gw % SS;
    int lp = g_len[0][b];
    float sm = 0.f, mx = NEGINF;
    for (int i = lane; i < SS; i += 32) {
        float v = g_cos[(b*SS + i)*SS + j];
        sm += v;
        if (i < lp) mx = fmaxf(mx, v);
    }
    #pragma unroll
    for (int o = 16; o; o >>= 1) {
        sm += __shfl_xor_sync(0xffffffffu, sm, o);
        mx = fmaxf(mx, __shfl_xor_sync(0xffffffffu, mx, o));
    }
    if (lane == 0) {
        g_colsum[gw] = sm;
        float* o = out + (size_t)(NTOK + b*SS + j)*OD;
        o[0] = mx;
        o[1] = sm / (float)lp;
    }
}

// ---------------- K3: attentive mean + max, fused (shared product cos*v) ---------
__global__ void k_att_h()  // reduce over j -> att_mean_h, att_max_h (per i)
{
    int b = blockIdx.x, it = blockIdx.y;
    __shared__ float cs[16][SS];
    int t = threadIdx.x;   // 128
    for (int e = t; e < 16*SS; e += 128) {
        int il = e >> 8, j = e & 255;
        cs[il][j] = g_cos[(b*SS + it*16 + il)*SS + j];
    }
    __syncthreads();
    int lh = g_len[1][b];
    int h = t;
    if (h < HH) {
        float sm[16], mx[16];
        #pragma unroll
        for (int il = 0; il < 16; il++) { sm[il] = 0.f; mx[il] = NEGINF; }
        for (int j = 0; j < lh; j++) {
            float c = __ldg(&g_ch[(b*SS + j)*HH + h]);
            #pragma unroll
            for (int il = 0; il < 16; il++) {
                float f = cs[il][j] * c;
                sm[il] += f;
                mx[il] = fmaxf(mx[il], f);
            }
        }
        #pragma unroll
        for (int il = 0; il < 16; il++) {
            int tok = b*SS + it*16 + il;
            g_att_mean[0][tok*HH + h] = sm[il] / fmaxf(g_rowsum[tok], EPSF);
            g_att_max[0][tok*HH + h] = mx[il];
        }
    }
}

__global__ void k_att_p()  // reduce over i -> att_mean_p, att_max_p (per j)
{
    int b = blockIdx.x, jt = blockIdx.y;
    __shared__ float cs[16][SS + 1];  // cs[jl][i], padded
    int t = threadIdx.x;   // 128
    for (int e = t; e < 16*SS; e += 128) {
        int i = e >> 4, jl = e & 15;
        cs[jl][i] = g_cos[(b*SS + i)*SS + jt*16 + jl];
    }
    __syncthreads();
    int lp = g_len[0][b];
    int h = t;
    if (h < HH) {
        float sm[16], mx[16];
        #pragma unroll
        for (int jl = 0; jl < 16; jl++) { sm[jl] = 0.f; mx[jl] = NEGINF; }
        for (int i = 0; i < lp; i++) {
            float c = __ldg(&g_cp[(b*SS + i)*HH + h]);
            #pragma unroll
            for (int jl = 0; jl < 16; jl++) {
                float f = cs[jl][i] * c;
                sm[jl] += f;
                mx[jl] = fmaxf(mx[jl], f);
            }
        }
        #pragma unroll
        for (int jl = 0; jl < 16; jl++) {
            int tok = b*SS + jt*16 + jl;
            g_att_mean[1][tok*HH + h] = sm[jl] / fmaxf(g_colsum[tok], EPSF);
            g_att_max[1][tok*HH + h] = mx[jl];
        }
    }
}

// ---------------- K5a: maxpool pairwise numerator GEMM ---------------------------
// num[b][m=i*P+p][j] = sum_h w_mp[p,h]^2 * cp[b,i,h] * ch[b,j,h]
// per batch: M=5120, N=256, K=100. 128x128 tile, 8x8 micro.
__global__ void __launch_bounds__(256) k_num(const float* __restrict__ w_mp)
{
    int b = blockIdx.z, mt = blockIdx.y, nt = blockIdx.x;
    __shared__ float As[10][128], Bs[10][128];
    int t = threadIdx.x, tx = t & 15, ty = t >> 4;
    float acc[8][8] = {};
    const float* cpb = g_cp + b*SS*HH;
    const float* chb = g_ch + b*SS*HH;
    for (int k0 = 0; k0 < HH; k0 += 10) {
        __syncthreads();
        for (int e = t; e < 128*10; e += 256) {
            int mm = e / 10, kc = e % 10;
            int m = mt*128 + mm;
            int i = m / PP, p = m - i*PP;
            float wv = w_mp[p*HH + k0 + kc];
            As[kc][mm] = cpb[i*HH + k0 + kc] * wv * wv;
            Bs[kc][mm] = chb[(nt*128 + mm)*HH + k0 + kc];
        }
        __syncthreads();
        #pragma unroll
        for (int kc = 0; kc < 10; kc++) {
            float4 a0 = *(const float4*)&As[kc][ty*8];
            float4 a1 = *(const float4*)&As[kc][ty*8 + 4];
            float4 b0 = *(const float4*)&Bs[kc][tx*8];
            float4 b1 = *(const float4*)&Bs[kc][tx*8 + 4];
            float a[8] = {a0.x,a0.y,a0.z,a0.w,a1.x,a1.y,a1.z,a1.w};
            float bb[8] = {b0.x,b0.y,b0.z,b0.w,b1.x,b1.y,b1.z,b1.w};
            #pragma unroll
            for (int r = 0; r < 8; r++)
                #pragma unroll
                for (int c = 0; c < 8; c++) acc[r][c] += a[r]*bb[c];
        }
    }
    #pragma unroll
    for (int r = 0; r < 8; r++) {
        int m = mt*128 + ty*8 + r;
        float* dst = g_num + ((size_t)b*5120 + m)*SS + nt*128 + tx*8;
        float4 v0 = make_float4(acc[r][0], acc[r][1], acc[r][2], acc[r][3]);
        float4 v1 = make_float4(acc[r][4], acc[r][5], acc[r][6], acc[r][7]);
        *(float4*)dst = v0;
        *(float4*)(dst + 4) = v1;
    }
}

// ---------------- K5b: maxpool p-side reduction over j ---------------------------
__global__ void k_mpred_p(float* __restrict__ out)
{
    int gw = blockIdx.x*8 + (threadIdx.x >> 5);   // 0..40959 : b*5120+m
    int lane = threadIdx.x & 31;
    int b = gw / 5120, m = gw % 5120;
    int i = m / PP, p = m % PP;
    float n1 = g_wn[0][1][b*5120 + m];
    int lh = g_len[1][b];
    const float* row = g_num + (size_t)gw*SS;
    const float* n2p = &g_wn[1][1][b*5120 + p];
    float sm = 0.f, mx = NEGINF;
    for (int j = lane; j < SS; j += 32) {
        float n2 = n2p[j*PP];
        float pw = row[j] / fmaxf(n1*n2, EPSF);
        sm += pw;
        if (j < lh) mx = fmaxf(mx, pw);
    }
    #pragma unroll
    for (int o = 16; o; o >>= 1) {
        sm += __shfl_xor_sync(0xffffffffu, sm, o);
        mx = fmaxf(mx, __shfl_xor_sync(0xffffffffu, mx, o));
    }
    if (lane == 0) {
        float* o = out + (size_t)(b*SS + i)*OD;
        o[23 + p] = mx;
        o[43 + p] = sm / (float)lh;
    }
}

// ---------------- K5c: maxpool h-side reduction over i ---------------------------
__global__ void k_mpred_h(float* __restrict__ out)
{
    int b = blockIdx.x, p = blockIdx.y;
    int j = threadIdx.x;  // 256
    __shared__ float sn1[SS];
    sn1[j] = g_wn[0][1][b*5120 + j*PP + p];
    __syncthreads();
    float n2 = g_wn[1][1][b*5120 + j*PP + p];
    int lp = g_len[0][b];
    float sm = 0.f, mx = NEGINF;
    const float* base = g_num + ((size_t)b*5120 + p)*SS + j;
    for (int i = 0; i < SS; i++) {
        float pw = base[(size_t)i*PP*SS] / fmaxf(sn1[i]*n2, EPSF);
        sm += pw;
        if (i < lp) mx = fmaxf(mx, pw);
    }
    float* o = out + (size_t)(NTOK + b*SS + j)*OD;
    o[23 + p] = mx;
    o[43 + p] = sm / (float)lp;
}

// ---------------- K4: multi-perspective match (full / att / maxatt) --------------
__global__ void k_match(const float* __restrict__ w_full, const float* __restrict__ w_att,
                        const float* __restrict__ w_ma, float* __restrict__ out)
{
    int which = blockIdx.y;  // 0 full, 1 att, 2 maxatt
    int side = blockIdx.z;
    int gw = blockIdx.x*8 + (threadIdx.x >> 5);   // b*S+i
    int lane = threadIdx.x & 31;
    int b = gw / SS;

    const float* v1 = (side ? g_ch : g_cp) + gw*HH;
    const float* wn1;
    const float* v2;
    const float* w;
    int col;
    if (which == 0) {
        wn1 = g_wn[side][0]; v2 = g_last[side ^ 1] + b*HH; w = w_full; col = 2;
    } else if (which == 1) {
        wn1 = g_wn[side][2]; v2 = g_att_mean[side] + gw*HH; w = w_att; col = 63;
    } else {
        wn1 = g_wn[side][3]; v2 = g_att_max[side] + gw*HH; w = w_ma; col = 84;
    }
    float* o = out + ((size_t)side*NTOK + gw)*OD;

    float r1[4], r2[4];
    float d = 0.f, q1 = 0.f, q2 = 0.f;
    #pragma unroll
    for (int k = 0; k < 4; k++) {
        int h = k*32 + lane;
        float a = (h < HH) ? v1[h] : 0.f;
        float c = (h < HH) ? v2[h] : 0.f;
        r1[k] = a; r2[k] = c;
        d += a*c; q1 += a*a; q2 += c*c;
    }
    #pragma unroll
    for (int of = 16; of; of >>= 1) {
        d  += __shfl_xor_sync(0xffffffffu, d, of);
        q1 += __shfl_xor_sync(0xffffffffu, q1, of);
        q2 += __shfl_xor_sync(0xffffffffu, q2, of);
    }
    if (lane == 0)
        o[col] = d / (fmaxf(sqrtf(q1), EPSF) * fmaxf(sqrtf(q2), EPSF));

    for (int p = 0; p < PP; p++) {
        float s12 = 0.f, s22 = 0.f;
        #pragma unroll
        for (int k = 0; k < 4; k++) {
            int h = k*32 + lane;
            float ww = (h < HH) ? w[p*HH + h] : 0.f;
            float w2 = ww*ww;
            s12 += w2 * r1[k] * r2[k];
            s22 += w2 * r2[k] * r2[k];
        }
        #pragma unroll
        for (int of = 16; of; of >>= 1) {
            s12 += __shfl_xor_sync(0xffffffffu, s12, of);
            s22 += __shfl_xor_sync(0xffffffffu, s22, of);
        }
        if (lane == 0) {
            float n1 = wn1[gw*PP + p];
            o[col + 1 + p] = s12 / (fmaxf(n1, EPSF) * fmaxf(sqrtf(s22), EPSF));
        }
    }
}

// ---------------- launcher --------------------------------------------------------
extern "C" void kernel_launch(void* const* d_in, const int* in_sizes, int n_in,
                              void* d_out, int out_size)
{
    const float* ctx_p  = (const float*)d_in[0];
    const int*   mask_p = (const int*)  d_in[1];
    const float* ctx_h  = (const float*)d_in[2];
    const int*   mask_h = (const int*)  d_in[3];
    const float* w_full = (const float*)d_in[4];
    const float* w_mp   = (const float*)d_in[5];
    const float* w_att  = (const float*)d_in[6];
    const float* w_ma   = (const float*)d_in[7];
    float* out = (float*)d_out;

    k_prep<<<512, 256>>>(ctx_p, mask_p, ctx_h, mask_h, w_full, w_mp, w_att, w_ma);
    k_len_last<<<1, 512>>>(mask_p, mask_h);
    k_cos<<<dim3(4, 4, BB), 256>>>();
    k_cosred_row<<<256, 256>>>(out);
    k_cosred_col<<<256, 256>>>(out);
    k_att_h<<<dim3(BB, 16), 128>>>();
    k_att_p<<<dim3(BB, 16), 128>>>();
    k_num<<<dim3(2, 40, BB), 256>>>(w_mp);
    k_mpred_p<<<5120, 256>>>(out);
    k_mpred_h<<<dim3(BB, PP), 256>>>(out);
    k_match<<<dim3(256, 3, 2), 256>>>(w_full, w_att, w_ma, out);
}

// round 2
// speedup vs baseline: 1.4384x; 1.4384x over previous
#include <cuda_runtime.h>
#include <math.h>

#define BB 8
#define SS 256
#define HH 100
#define PP 20
#define EPSF 1e-8f
#define NTOK (BB*SS)      // 2048 per side
#define OD 105
#define NEGINF -3.0e38f

// ---------------- scratch (device globals; no runtime allocation) ----------------
__device__ float g_cp[NTOK*HH], g_ch[NTOK*HH];     // masked contexts, row-major [tok][h]
__device__ float g_cpT[BB*HH*SS], g_chT[BB*HH*SS]; // transposed [b][h][i]
__device__ float g_aT[BB*PP*HH*SS];                // weighted A' [b][p][h][i]  (16.4MB)
__device__ float g_np[NTOK], g_nh[NTOK];           // unweighted norms
__device__ float g_wn[2][4][NTOK*PP];              // [side][w: full,maxpool,att,maxatt][tok*P+p]
__device__ int   g_len[2][BB];
__device__ float g_last[2][BB*HH];
__device__ float g_cos[BB*SS*SS];
__device__ float g_rowsum[NTOK], g_colsum[NTOK];
__device__ float g_att_mean[2][NTOK*HH];
__device__ float g_att_max[2][NTOK*HH];
__device__ float g_pw[BB*PP*SS*SS];                // pw [b][p][i][j]  (42MB)

// ---------------- K0: per-token prep: masked ctx, norms, weighted norms ----------
__global__ void k_prep(const float* __restrict__ ctx_p, const int* __restrict__ mask_p,
                       const float* __restrict__ ctx_h, const int* __restrict__ mask_h,
                       const float* __restrict__ w_full, const float* __restrict__ w_mp,
                       const float* __restrict__ w_att, const float* __restrict__ w_ma)
{
    __shared__ float vsq[8][HH];
    int wl = threadIdx.x >> 5;
    int lane = threadIdx.x & 31;
    int gw = blockIdx.x * 8 + wl;            // 0..4095
    int side = gw / NTOK;
    int tok = gw % NTOK;
    const float* ctx = side ? ctx_h : ctx_p;
    const int* mask = side ? mask_h : mask_p;
    float* dst = side ? g_ch : g_cp;
    float m = (float)mask[tok];
    float q = 0.f;
    for (int h = lane; h < HH; h += 32) {
        float v = ctx[tok*HH + h] * m;
        dst[tok*HH + h] = v;
        float v2 = v * v;
        vsq[wl][h] = v2;
        q += v2;
    }
    #pragma unroll
    for (int o = 16; o; o >>= 1) q += __shfl_xor_sync(0xffffffffu, q, o);
    if (lane == 0) (side ? g_nh : g_np)[tok] = sqrtf(q);
    __syncwarp();
    const float* ws[4] = {w_full, w_mp, w_att, w_ma};
    for (int c = lane; c < 4*PP; c += 32) {
        int w = c / PP, p = c % PP;
        const float* wr = ws[w] + p*HH;
        float s = 0.f;
        #pragma unroll 4
        for (int h = 0; h < HH; h++) { float ww = wr[h]; s += ww*ww*vsq[wl][h]; }
        g_wn[side][w][tok*PP + p] = sqrtf(s);
    }
}

// ---------------- K0b: lengths + last valid token vectors ------------------------
__global__ void k_len_last(const int* __restrict__ mask_p, const int* __restrict__ mask_h)
{
    int w = threadIdx.x >> 5;        // 0..15
    int lane = threadIdx.x & 31;
    int side = w / BB, b = w % BB;
    const int* mask = side ? mask_h : mask_p;
    int s = 0;
    for (int j = lane; j < SS; j += 32) s += mask[b*SS + j];
    #pragma unroll
    for (int o = 16; o; o >>= 1) s += __shfl_xor_sync(0xffffffffu, s, o);
    if (lane == 0) g_len[side][b] = s;
    s = __shfl_sync(0xffffffffu, s, 0);
    int last = s > 0 ? s - 1 : 0;
    const float* src = (side ? g_ch : g_cp) + (b*SS + last)*HH;
    float* dst = g_last[side] + b*HH;
    for (int h = lane; h < HH; h += 32) dst[h] = src[h];
}

// ---------------- K0c: transpose + weighted A' build ------------------------------
// side 0: cp -> g_cpT and g_aT (20 weighted copies). side 1: ch -> g_chT.
__global__ void __launch_bounds__(256) k_trans(const float* __restrict__ w_mp)
{
    int i0 = blockIdx.x * 64, b = blockIdx.y, side = blockIdx.z;
    __shared__ float tile[64][101];
    __shared__ float wsq[PP*HH];
    int t = threadIdx.x;
    const float* src = (side ? g_ch : g_cp) + (b*SS + i0)*HH;
    for (int e = t; e < 64*HH; e += 256) tile[e/HH][e%HH] = src[e];
    if (side == 0)
        for (int e = t; e < PP*HH; e += 256) { float w = w_mp[e]; wsq[e] = w*w; }
    __syncthreads();
    int i = t & 63, g = t >> 6;
    float* dstT = (side ? g_chT : g_cpT) + b*HH*SS + i0 + i;
    for (int h = g; h < HH; h += 4) dstT[h*SS] = tile[i][h];
    if (side == 0) {
        for (int p = 0; p < PP; p++) {
            float* dA = g_aT + (size_t)((b*PP + p)*HH)*SS + i0 + i;
            #pragma unroll 5
            for (int h = g; h < HH; h += 4) dA[h*SS] = wsq[p*HH + h]*tile[i][h];
        }
    }
}

// ---------------- K1: pairwise cosine GEMM, row-reduction fused -------------------
// block: 32 i-rows x full 256 j. micro 4x8 (strided cols). grid (8 itiles, 8 b).
__global__ void __launch_bounds__(256) k_cos(float* __restrict__ out)
{
    int b = blockIdx.y, i0 = blockIdx.x * 32;
    __shared__ float As[20][32], Bs[20][256], nhs[SS];
    int t = threadIdx.x, tx = t & 31, ty = t >> 5;
    float acc[4][8] = {};
    const float* gA = g_cpT + b*HH*SS + i0;
    const float* gB = g_chT + b*HH*SS;
    if (t < SS) nhs[t] = fmaxf(g_nh[b*SS + t], EPSF);
    for (int k0 = 0; k0 < HH; k0 += 20) {
        __syncthreads();
        for (int e = t; e < 640; e += 256)
            As[e >> 5][e & 31] = gA[(k0 + (e >> 5))*SS + (e & 31)];
        for (int f = t; f < 1280; f += 256) {
            int kc = f >> 6, jj = (f & 63)*4;
            *(float4*)&Bs[kc][jj] = *(const float4*)&gB[(k0 + kc)*SS + jj];
        }
        __syncthreads();
        #pragma unroll
        for (int kc = 0; kc < 20; kc++) {
            float bb[8];
            #pragma unroll
            for (int c = 0; c < 8; c++) bb[c] = Bs[kc][tx + 32*c];
            #pragma unroll
            for (int r = 0; r < 4; r++) {
                float a = As[kc][ty*4 + r];
                #pragma unroll
                for (int c = 0; c < 8; c++) acc[r][c] += a*bb[c];
            }
        }
    }
    int lh = g_len[1][b];
    #pragma unroll
    for (int r = 0; r < 4; r++) {
        int i = i0 + ty*4 + r;
        float ni = fmaxf(g_np[b*SS + i], EPSF);
        float sm = 0.f, mx = NEGINF;
        #pragma unroll
        for (int c = 0; c < 8; c++) {
            int j = tx + 32*c;
            float v = acc[r][c] / (ni*nhs[j]);
            g_cos[(b*SS + i)*SS + j] = v;
            sm += v;
            if (j < lh) mx = fmaxf(mx, v);
        }
        #pragma unroll
        for (int o = 16; o; o >>= 1) {
            sm += __shfl_xor_sync(0xffffffffu, sm, o);
            mx = fmaxf(mx, __shfl_xor_sync(0xffffffffu, mx, o));
        }
        if (tx == 0) {
            g_rowsum[b*SS + i] = sm;
            float* o = out + (size_t)(b*SS + i)*OD;
            o[0] = mx;
            o[1] = sm / (float)lh;
        }
    }
}

// ---------------- K2: cos column reduction ----------------------------------------
__global__ void k_cosred_col(float* __restrict__ out)
{
    int gw = blockIdx.x*8 + (threadIdx.x >> 5);   // b*S+j
    int lane = threadIdx.x & 31;
    int b = gw / SS, j = gw % SS;
    int lp = g_len[0][b];
    float sm = 0.f, mx = NEGINF;
    for (int i = lane; i < SS; i += 32) {
        float v = g_cos[(b*SS + i)*SS + j];
        sm += v;
        if (i < lp) mx = fmaxf(mx, v);
    }
    #pragma unroll
    for (int o = 16; o; o >>= 1) {
        sm += __shfl_xor_sync(0xffffffffu, sm, o);
        mx = fmaxf(mx, __shfl_xor_sync(0xffffffffu, mx, o));
    }
    if (lane == 0) {
        g_colsum[gw] = sm;
        float* o = out + (size_t)(NTOK + b*SS + j)*OD;
        o[0] = mx;
        o[1] = sm / (float)lp;
    }
}

// ---------------- K3: attentive mean + max, fused ---------------------------------
__global__ void k_att_h()  // reduce over j -> att_mean_h, att_max_h (per i)
{
    int b = blockIdx.x, it = blockIdx.y;
    __shared__ float cs[8][SS];
    int t = threadIdx.x;   // 128
    for (int e = t; e < 8*SS; e += 128) {
        int il = e >> 8, j = e & 255;
        cs[il][j] = g_cos[(b*SS + it*8 + il)*SS + j];
    }
    __syncthreads();
    int lh = g_len[1][b];
    int h = t;
    if (h < HH) {
        float sm[8], mx[8];
        #pragma unroll
        for (int il = 0; il < 8; il++) { sm[il] = 0.f; mx[il] = NEGINF; }
        for (int j = 0; j < lh; j++) {
            float c = __ldg(&g_ch[(b*SS + j)*HH + h]);
            #pragma unroll
            for (int il = 0; il < 8; il++) {
                float f = cs[il][j] * c;
                sm[il] += f;
                mx[il] = fmaxf(mx[il], f);
            }
        }
        #pragma unroll
        for (int il = 0; il < 8; il++) {
            int tok = b*SS + it*8 + il;
            g_att_mean[0][tok*HH + h] = sm[il] / fmaxf(g_rowsum[tok], EPSF);
            g_att_max[0][tok*HH + h] = mx[il];
        }
    }
}

__global__ void k_att_p()  // reduce over i -> att_mean_p, att_max_p (per j)
{
    int b = blockIdx.x, jt = blockIdx.y;
    __shared__ float cs[8][SS + 1];
    int t = threadIdx.x;   // 128
    for (int e = t; e < 8*SS; e += 128) {
        int i = e >> 3, jl = e & 7;
        cs[jl][i] = g_cos[(b*SS + i)*SS + jt*8 + jl];
    }
    __syncthreads();
    int lp = g_len[0][b];
    int h = t;
    if (h < HH) {
        float sm[8], mx[8];
        #pragma unroll
        for (int jl = 0; jl < 8; jl++) { sm[jl] = 0.f; mx[jl] = NEGINF; }
        for (int i = 0; i < lp; i++) {
            float c = __ldg(&g_cp[(b*SS + i)*HH + h]);
            #pragma unroll
            for (int jl = 0; jl < 8; jl++) {
                float f = cs[jl][i] * c;
                sm[jl] += f;
                mx[jl] = fmaxf(mx[jl], f);
            }
        }
        #pragma unroll
        for (int jl = 0; jl < 8; jl++) {
            int tok = b*SS + jt*8 + jl;
            g_att_mean[1][tok*HH + h] = sm[jl] / fmaxf(g_colsum[tok], EPSF);
            g_att_max[1][tok*HH + h] = mx[jl];
        }
    }
}

// ---------------- K5: maxpool pairwise GEMM with fused p-side reduction -----------
// per (b,p): C[i,j] = sum_h A'[h,i] * chT[h,j]. block: 64 i-rows x full 256 j.
// micro 8x8 with f32x2 packed FMA (pairs along j). grid (4 itiles, 160 bp).
__global__ void __launch_bounds__(256) k_pw(float* __restrict__ out)
{
    int bp = blockIdx.y; int b = bp / PP, p = bp % PP;
    int i0 = blockIdx.x * 64;
    __shared__ float As[20][128];   // duplicated pairs: As[kc][2m]=As[kc][2m+1]=A'[k][m]
    __shared__ float Bs[20][256];
    __shared__ float n1s[64], n2s[256];
    int t = threadIdx.x, tx = t & 31, ty = t >> 5;

    if (t < 64)  n1s[t] = g_wn[0][1][(b*SS + i0 + t)*PP + p];
    if (t < 256) n2s[t] = g_wn[1][1][(b*SS + t)*PP + p];

    unsigned long long acc[8][4];
    #pragma unroll
    for (int r = 0; r < 8; r++)
        #pragma unroll
        for (int c = 0; c < 4; c++) acc[r][c] = 0ull;

    const float* gA = g_aT + (size_t)(bp*HH)*SS + i0;
    const float* gB = g_chT + b*HH*SS;

    for (int k0 = 0; k0 < HH; k0 += 20) {
        __syncthreads();
        #pragma unroll
        for (int q = 0; q < 5; q++) {
            int e = t + 256*q;                       // 1280 A elems
            int kc = e >> 6, mm = e & 63;
            float v = gA[(k0 + kc)*SS + mm];
            float2 d; d.x = v; d.y = v;
            *(float2*)&As[kc][mm*2] = d;
        }
        #pragma unroll
        for (int q = 0; q < 5; q++) {
            int f = t + 256*q;                       // 1280 float4 B loads
            int kc = f >> 6, jj = (f & 63)*4;
            *(float4*)&Bs[kc][jj] = *(const float4*)&gB[(k0 + kc)*SS + jj];
        }
        __syncthreads();
        #pragma unroll
        for (int kc = 0; kc < 20; kc++) {
            unsigned long long b2[4];
            #pragma unroll
            for (int c = 0; c < 4; c++)
                b2[c] = *(const unsigned long long*)&Bs[kc][2*tx + 64*c];
            #pragma unroll
            for (int r = 0; r < 8; r++) {
                unsigned long long a2 = *(const unsigned long long*)&As[kc][(ty*8 + r)*2];
                #pragma unroll
                for (int c = 0; c < 4; c++)
                    asm("fma.rn.f32x2 %0, %1, %2, %0;"
                        : "+l"(acc[r][c]) : "l"(a2), "l"(b2[c]));
            }
        }
    }

    int lh = g_len[1][b];
    float inv_lh = 1.0f / (float)lh;
    #pragma unroll
    for (int r = 0; r < 8; r++) {
        int i = i0 + ty*8 + r;
        float n1 = n1s[ty*8 + r];
        float sm = 0.f, mx = NEGINF;
        float* rowp = g_pw + ((size_t)bp*SS + i)*SS;
        #pragma unroll
        for (int c = 0; c < 4; c++) {
            unsigned lo, hi;
            asm("mov.b64 {%0, %1}, %2;" : "=r"(lo), "=r"(hi) : "l"(acc[r][c]));
            int j0 = 2*tx + 64*c;
            float pw0 = __uint_as_float(lo) / fmaxf(n1*n2s[j0], EPSF);
            float pw1 = __uint_as_float(hi) / fmaxf(n1*n2s[j0 + 1], EPSF);
            float2 st; st.x = pw0; st.y = pw1;
            *(float2*)&rowp[j0] = st;
            sm += pw0 + pw1;
            if (j0 < lh)     mx = fmaxf(mx, pw0);
            if (j0 + 1 < lh) mx = fmaxf(mx, pw1);
        }
        #pragma unroll
        for (int o = 16; o; o >>= 1) {
            sm += __shfl_xor_sync(0xffffffffu, sm, o);
            mx = fmaxf(mx, __shfl_xor_sync(0xffffffffu, mx, o));
        }
        if (tx == 0) {
            float* o = out + (size_t)(b*SS + i)*OD;
            o[23 + p] = mx;
            o[43 + p] = sm * inv_lh;
        }
    }
}

// ---------------- K5c: maxpool h-side reduction over i (coalesced columns) --------
__global__ void k_pw_h(float* __restrict__ out)
{
    int bp = blockIdx.x; int b = bp / PP, p = bp % PP;
    int j = threadIdx.x;  // 256
    int lp = g_len[0][b];
    const float* base = g_pw + ((size_t)bp*SS)*SS + j;
    float sm = 0.f, mx = NEGINF;
    #pragma unroll 8
    for (int i = 0; i < SS; i++) {
        float v = base[(size_t)i*SS];
        sm += v;
        if (i < lp) mx = fmaxf(mx, v);
    }
    float* o = out + (size_t)(NTOK + b*SS + j)*OD;
    o[23 + p] = mx;
    o[43 + p] = sm / (float)lp;
}

// ---------------- K4: multi-perspective match (full / att / maxatt) --------------
__global__ void k_match(const float* __restrict__ w_full, const float* __restrict__ w_att,
                        const float* __restrict__ w_ma, float* __restrict__ out)
{
    int which = blockIdx.y;  // 0 full, 1 att, 2 maxatt
    int side = blockIdx.z;
    int gw = blockIdx.x*8 + (threadIdx.x >> 5);   // b*S+i
    int lane = threadIdx.x & 31;
    int b = gw / SS;

    const float* v1 = (side ? g_ch : g_cp) + gw*HH;
    const float* wn1;
    const float* v2;
    const float* w;
    int col;
    if (which == 0) {
        wn1 = g_wn[side][0]; v2 = g_last[side ^ 1] + b*HH; w = w_full; col = 2;
    } else if (which == 1) {
        wn1 = g_wn[side][2]; v2 = g_att_mean[side] + gw*HH; w = w_att; col = 63;
    } else {
        wn1 = g_wn[side][3]; v2 = g_att_max[side] + gw*HH; w = w_ma; col = 84;
    }
    float* o = out + ((size_t)side*NTOK + gw)*OD;

    float r1[4], r2[4];
    float d = 0.f, q1 = 0.f, q2 = 0.f;
    #pragma unroll
    for (int k = 0; k < 4; k++) {
        int h = k*32 + lane;
        float a = (h < HH) ? v1[h] : 0.f;
        float c = (h < HH) ? v2[h] : 0.f;
        r1[k] = a; r2[k] = c;
        d += a*c; q1 += a*a; q2 += c*c;
    }
    #pragma unroll
    for (int of = 16; of; of >>= 1) {
        d  += __shfl_xor_sync(0xffffffffu, d, of);
        q1 += __shfl_xor_sync(0xffffffffu, q1, of);
        q2 += __shfl_xor_sync(0xffffffffu, q2, of);
    }
    if (lane == 0)
        o[col] = d / (fmaxf(sqrtf(q1), EPSF) * fmaxf(sqrtf(q2), EPSF));

    for (int p = 0; p < PP; p++) {
        float s12 = 0.f, s22 = 0.f;
        #pragma unroll
        for (int k = 0; k < 4; k++) {
            int h = k*32 + lane;
            float ww = (h < HH) ? w[p*HH + h] : 0.f;
            float w2 = ww*ww;
            s12 += w2 * r1[k] * r2[k];
            s22 += w2 * r2[k] * r2[k];
        }
        #pragma unroll
        for (int of = 16; of; of >>= 1) {
            s12 += __shfl_xor_sync(0xffffffffu, s12, of);
            s22 += __shfl_xor_sync(0xffffffffu, s22, of);
        }
        if (lane == 0) {
            float n1 = wn1[gw*PP + p];
            o[col + 1 + p] = s12 / (fmaxf(n1, EPSF) * fmaxf(sqrtf(s22), EPSF));
        }
    }
}

// ---------------- launcher --------------------------------------------------------
extern "C" void kernel_launch(void* const* d_in, const int* in_sizes, int n_in,
                              void* d_out, int out_size)
{
    const float* ctx_p  = (const float*)d_in[0];
    const int*   mask_p = (const int*)  d_in[1];
    const float* ctx_h  = (const float*)d_in[2];
    const int*   mask_h = (const int*)  d_in[3];
    const float* w_full = (const float*)d_in[4];
    const float* w_mp   = (const float*)d_in[5];
    const float* w_att  = (const float*)d_in[6];
    const float* w_ma   = (const float*)d_in[7];
    float* out = (float*)d_out;

    k_prep<<<512, 256>>>(ctx_p, mask_p, ctx_h, mask_h, w_full, w_mp, w_att, w_ma);
    k_len_last<<<1, 512>>>(mask_p, mask_h);
    k_trans<<<dim3(4, BB, 2), 256>>>(w_mp);
    k_cos<<<dim3(8, BB), 256>>>(out);
    k_cosred_col<<<256, 256>>>(out);
    k_att_h<<<dim3(BB, 32), 128>>>();
    k_att_p<<<dim3(BB, 32), 128>>>();
    k_pw<<<dim3(4, BB*PP), 256>>>(out);
    k_pw_h<<<BB*PP, 256>>>(out);
    k_match<<<dim3(256, 3, 2), 256>>>(w_full, w_att, w_ma, out);
}